// round 11
// baseline (speedup 1.0000x reference)
#include <cuda_runtime.h>
#include <math.h>

// Problem constants (fixed by setup_inputs)
#define BB 8
#define SS 4096
#define DD 512
#define NCHUNK 64
#define SROWS (SS / NCHUNK)   // 64 rows per k1 block
#define PP 98                 // sampled partitions
#define KMAXP 6
#define MAXPART 100
#define MASK_WORDS_PER_P (KMAXP * DD / 4)   // 768 u32 words per partition (u8 view)

// Scratch (no allocations allowed -> __device__ globals).
// __align__(16): accessed through float4 casts.
__device__ __align__(16) float g_partE[NCHUNK * BB * DD];   // 1 MB
__device__ __align__(16) float g_partT[NCHUNK * BB * DD];
__device__ __align__(16) float g_sumE[BB * DD];
__device__ __align__(16) float g_sumT[BB * DD];
__device__ float g_Hfull[BB];                 // per-batch full-flatten entropy
__device__ float g_hsingle[BB];               // per-batch sum_d H_sd
__device__ float g_hpk[BB * PP];              // per (b,p): sum_k H_pk
__device__ int   g_cntB[BB] = {0};            // per-batch k1 completion counters
__device__ int   g_cnt = 0;                   // k3 completion counter

// ---------------------------------------------------------------------------
// k1: streaming pass + fused per-batch reduce (threadfence-reduction).
// grid = (NCHUNK, B) = 512 blocks, 512 threads.
// Streaming: thread (sub=t/128, dt=t%128) reads float4 column dt of rows
// 4i+sub (16 LDG.128); the 4 subs combine in shared; t<128 write partials.
// Then each block bumps g_cntB[b]; the LAST block of batch b reduces all 64
// chunk partials (L2-resident), writes g_sumE/g_sumT, per-d singleton
// entropies, and the per-batch scalars g_Hfull[b] / g_hsingle[b].
// Election is order-independent -> deterministic. Counters self-reset.
// ---------------------------------------------------------------------------
__global__ void __launch_bounds__(512) k1_stream(const float* __restrict__ x) {
    const int chunk = blockIdx.x;
    const int b     = blockIdx.y;
    const int t     = threadIdx.x;
    const int sub   = t >> 7;     // 0..3: row subset
    const int dt    = t & 127;    // float4 column

    const float4* xp = reinterpret_cast<const float4*>(
        x + ((size_t)b * SS + (size_t)chunk * SROWS) * DD)
        + (size_t)sub * (DD / 4) + dt;

    float e0 = 0.f, e1 = 0.f, e2 = 0.f, e3 = 0.f;
    float t0 = 0.f, t1 = 0.f, t2 = 0.f, t3 = 0.f;
    #pragma unroll 4
    for (int i = 0; i < SROWS / 4; i++) {
        const float4 v = xp[(size_t)i * DD];   // advance 4 rows (= DD float4)
        const float p0 = __expf(v.x), p1 = __expf(v.y),
                    p2 = __expf(v.z), p3 = __expf(v.w);
        e0 += p0; e1 += p1; e2 += p2; e3 += p3;
        t0 = fmaf(p0, v.x, t0);
        t1 = fmaf(p1, v.y, t1);
        t2 = fmaf(p2, v.z, t2);
        t3 = fmaf(p3, v.w, t3);
    }

    __shared__ __align__(16) float4 sE4[4][128], sT4[4][128];
    sE4[sub][dt] = make_float4(e0, e1, e2, e3);
    sT4[sub][dt] = make_float4(t0, t1, t2, t3);
    __syncthreads();
    if (t < 128) {
        float4 ae = sE4[0][t], at = sT4[0][t];
        #pragma unroll
        for (int s = 1; s < 4; s++) {
            const float4 oe = sE4[s][t], ot = sT4[s][t];
            ae.x += oe.x; ae.y += oe.y; ae.z += oe.z; ae.w += oe.w;
            at.x += ot.x; at.y += ot.y; at.z += ot.z; at.w += ot.w;
        }
        const int base = (chunk * BB + b) * DD;   // chunk-major
        reinterpret_cast<float4*>(g_partE + base)[t] = ae;
        reinterpret_cast<float4*>(g_partT + base)[t] = at;
    }

    // ---- election: last block of this batch reduces ----
    __shared__ int s_last;
    __threadfence();
    __syncthreads();
    if (t == 0) s_last = (atomicAdd(&g_cntB[b], 1) == NCHUNK - 1);
    __syncthreads();
    if (!s_last) return;

    // ===== fused k2: reduce 64 chunks for batch b (512 threads = 512 d) =====
    const int d = t;
    float E = 0.f, T = 0.f;
    #pragma unroll 8
    for (int c = 0; c < NCHUNK; c++) {
        const int idx = (c * BB + b) * DD + d;
        E += g_partE[idx];
        T += g_partT[idx];
    }
    g_sumE[b * DD + d] = E;
    g_sumT[b * DD + d] = T;

    const float h = logf(E) - T / E;          // singleton entropy for (b,d)

    float se = E, st = T, sh = h;
    #pragma unroll
    for (int o = 16; o > 0; o >>= 1) {
        se += __shfl_down_sync(0xffffffffu, se, o);
        st += __shfl_down_sync(0xffffffffu, st, o);
        sh += __shfl_down_sync(0xffffffffu, sh, o);
    }
    __shared__ float wE[16], wT[16], wH[16];
    const int w = t >> 5, l = t & 31;
    if (l == 0) { wE[w] = se; wT[w] = st; wH[w] = sh; }
    __syncthreads();
    if (t < 32) {
        se = (t < 16) ? wE[t] : 0.f;
        st = (t < 16) ? wT[t] : 0.f;
        sh = (t < 16) ? wH[t] : 0.f;
        #pragma unroll
        for (int o = 8; o > 0; o >>= 1) {
            se += __shfl_down_sync(0xffffffffu, se, o);
            st += __shfl_down_sync(0xffffffffu, st, o);
            sh += __shfl_down_sync(0xffffffffu, sh, o);
        }
        if (t == 0) {
            g_hsingle[b] = sh;
            g_Hfull[b]   = logf(se) - st / se;
            atomicExch(&g_cntB[b], 0);        // self-reset for graph replays
        }
    }
}

// ---------------------------------------------------------------------------
// k3: sampled partitions + fused finalize (threadfence-reduction pattern).
// grid = (P, B) = 784 blocks, 128 threads x 4 d's.
// Mask dtype detection per block: u8 layout guarantees nonzero bytes at
// offset ≡1 (mod 4) inside this partition's region; int32/float32 0/1 layout
// guarantees all-zero there; range is in-bounds for all candidate dtypes.
// Last block runs the k4 tail; counter self-resets for graph replays.
// ---------------------------------------------------------------------------
__global__ void __launch_bounds__(128) k3_parts(
    const void*  __restrict__ masks_raw,
    const float* __restrict__ es,  const float* __restrict__ iw,
    const float* __restrict__ W1,  const float* __restrict__ b1,
    const float* __restrict__ W2,  const float* __restrict__ b2,
    const float* __restrict__ W3,  const float* __restrict__ b3,
    float* __restrict__ out)
{
    const int p = blockIdx.x;
    const int b = blockIdx.y;
    const int t = threadIdx.x;
    const unsigned int* mw = (const unsigned int*)masks_raw;

    unsigned int v = 0;
    #pragma unroll
    for (int j = t; j < MASK_WORDS_PER_P; j += 128)
        v |= mw[p * MASK_WORDS_PER_P + j] & 0x0000FF00u;
    const bool isU8 = (__syncthreads_or(v != 0) != 0);

    int a0 = 0, a1 = 0, a2 = 0, a3 = 0;
    if (isU8) {
        #pragma unroll
        for (int k = KMAXP - 1; k >= 0; k--) {
            const unsigned int wm = mw[(p * KMAXP + k) * (DD / 4) + t];
            if (wm & 0x000000FFu) a0 = k;
            if (wm & 0x0000FF00u) a1 = k;
            if (wm & 0x00FF0000u) a2 = k;
            if (wm & 0xFF000000u) a3 = k;
        }
    } else {
        const uint4* m4 = (const uint4*)masks_raw;
        #pragma unroll
        for (int k = KMAXP - 1; k >= 0; k--) {
            const uint4 wm = m4[(p * KMAXP + k) * (DD / 4) + t];
            if (wm.x) a0 = k;
            if (wm.y) a1 = k;
            if (wm.z) a2 = k;
            if (wm.w) a3 = k;
        }
    }

    const float4 e4 = reinterpret_cast<const float4*>(g_sumE + b * DD)[t];
    const float4 t4 = reinterpret_cast<const float4*>(g_sumT + b * DD)[t];

    float zk[KMAXP], tk[KMAXP];
    #pragma unroll
    for (int k = 0; k < KMAXP; k++) {
        zk[k] = (a0 == k ? e4.x : 0.f) + (a1 == k ? e4.y : 0.f)
              + (a2 == k ? e4.z : 0.f) + (a3 == k ? e4.w : 0.f);
        tk[k] = (a0 == k ? t4.x : 0.f) + (a1 == k ? t4.y : 0.f)
              + (a2 == k ? t4.z : 0.f) + (a3 == k ? t4.w : 0.f);
    }

    #pragma unroll
    for (int o = 16; o > 0; o >>= 1) {
        #pragma unroll
        for (int k = 0; k < KMAXP; k++) {
            zk[k] += __shfl_down_sync(0xffffffffu, zk[k], o);
            tk[k] += __shfl_down_sync(0xffffffffu, tk[k], o);
        }
    }
    __shared__ float sz[4][KMAXP], sst[4][KMAXP];
    const int w = t >> 5, l = t & 31;
    if (l == 0) {
        #pragma unroll
        for (int k = 0; k < KMAXP; k++) { sz[w][k] = zk[k]; sst[w][k] = tk[k]; }
    }
    __syncthreads();
    if (t == 0) {
        float hsum = 0.f;
        #pragma unroll
        for (int k = 0; k < KMAXP; k++) {
            float Z = sz[0][k] + sz[1][k] + sz[2][k] + sz[3][k];
            float T = sst[0][k] + sst[1][k] + sst[2][k] + sst[3][k];
            if (Z > 0.f) hsum += logf(Z) - T / Z;   // empty bin -> 0
        }
        g_hpk[b * PP + p] = hsum;
    }

    // ---- completion count: is this the last block? ----
    __shared__ int s_last;
    __threadfence();
    __syncthreads();
    if (t == 0) s_last = (atomicAdd(&g_cnt, 1) == PP * BB - 1);
    __syncthreads();
    if (!s_last) return;

    // ======================= k4 tail (one block) =======================
    __shared__ float sh_min[128];
    __shared__ float sh_es[128];
    __shared__ float shF[BB], shS[BB];
    __shared__ __align__(16) float sh_w2[16 * 32];
    __shared__ float sh_w1[32], sh_b1[32], sh_b2[16], sh_w3[16], sh_b3;
    __shared__ float sh_h1[32];

    // cooperative weight prefetch (issued first; overlaps other loads)
    reinterpret_cast<float4*>(sh_w2)[t] = reinterpret_cast<const float4*>(W2)[t];
    if (t < 32) { sh_w1[t] = W1[t]; sh_b1[t] = b1[t]; }
    else if (t < 48) { sh_b2[t - 32] = b2[t - 32]; }
    else if (t < 64) { sh_w3[t - 48] = W3[t - 48]; }
    else if (t == 64) { sh_b3 = b3[0]; }

    if (t >= 96 && t < 96 + BB) {
        const int bb = t - 96;
        shF[bb] = g_Hfull[bb];
        shS[bb] = g_hsingle[bb];
    }

    float se = 0.f;
    #pragma unroll
    for (int i = 0; i < 4; i++) se += es[t + i * 128];
    sh_es[t] = se;
    __syncthreads();

    float wv = INFINITY;
    if (t < MAXPART) {
        float h;
        if (t == 0) {
            float s = 0.f;
            #pragma unroll
            for (int bb = 0; bb < BB; bb++) s += shF[bb];
            h = s / (float)BB;
        } else if (t == 1) {
            float s = 0.f;
            #pragma unroll
            for (int bb = 0; bb < BB; bb++) s += shS[bb];
            h = s / (float)BB;
        } else {
            float s = 0.f;
            #pragma unroll
            for (int bb = 0; bb < BB; bb++) s += g_hpk[bb * PP + (t - 2)];
            h = s / (float)BB;
        }
        const float sg = 1.f / (1.f + expf(-iw[t]));
        wv = h * sg;
    }
    sh_min[t] = wv;
    __syncthreads();

    #pragma unroll
    for (int o = 64; o > 0; o >>= 1) {
        if (t < o) {
            sh_min[t] = fminf(sh_min[t], sh_min[t + o]);
            sh_es[t] += sh_es[t + o];
        }
        __syncthreads();
    }

    if (t < 32) {
        float s = 0.f;
        #pragma unroll
        for (int bb = 0; bb < BB; bb++) s += shF[bb];
        const float h_whole = s / (float)BB;
        const float es_mean = sh_es[0] / (float)DD;

        const float raw_phi = es_mean * h_whole - sh_min[0];
        float z = fminf(fmaxf(raw_phi * 0.1f, 0.f), 1.f);

        sh_h1[t] = fmaxf(fmaf(z, sh_w1[t], sh_b1[t]), 0.f);   // h1, one per lane
        __syncwarp();

        float acc = 0.f;
        if (t < 16) {
            float a = sh_b2[t];
            #pragma unroll
            for (int j = 0; j < 32; j++) a = fmaf(sh_w2[t * 32 + j], sh_h1[j], a);
            acc = fmaxf(a, 0.f) * sh_w3[t];                    // h2[t] * W3[t]
        }
        #pragma unroll
        for (int o = 16; o > 0; o >>= 1) acc += __shfl_down_sync(0xffffffffu, acc, o);

        if (t == 0) {
            out[0] = 1.f / (1.f + expf(-(acc + sh_b3)));
            atomicExch(&g_cnt, 0);    // self-reset for the next graph replay
        }
    }
}

// ---------------------------------------------------------------------------
extern "C" void kernel_launch(void* const* d_in, const int* in_sizes, int n_in,
                              void* d_out, int out_size) {
    const float* x  = (const float*)d_in[0];
    const float* es = (const float*)d_in[1];
    const float* iw = (const float*)d_in[2];
    const float* W1 = (const float*)d_in[3];
    const float* b1 = (const float*)d_in[4];
    const float* W2 = (const float*)d_in[5];
    const float* b2 = (const float*)d_in[6];
    const float* W3 = (const float*)d_in[7];
    const float* b3 = (const float*)d_in[8];
    const void*  masks = (const void*)d_in[9];

    k1_stream<<<dim3(NCHUNK, BB), 512>>>(x);
    k3_parts<<<dim3(PP, BB), 128>>>(masks, es, iw, W1, b1, W2, b2, W3, b3,
                                    (float*)d_out);
}

// round 12
// speedup vs baseline: 1.3053x; 1.3053x over previous
#include <cuda_runtime.h>
#include <math.h>

// Problem constants (fixed by setup_inputs)
#define BB 8
#define SS 4096
#define DD 512
#define NCHUNK 64
#define SROWS (SS / NCHUNK)   // 64 rows per k1 block
#define NGRP 16               // k2 d-slices of 32
#define PP 98                 // sampled partitions
#define KMAXP 6
#define MAXPART 100
#define MASK_WORDS_PER_P (KMAXP * DD / 4)   // 768 u32 words per partition (u8 view)

// Scratch (no allocations allowed -> __device__ globals).
// __align__(16): accessed through float4/uchar4 casts.
__device__ __align__(16) float g_partE[NCHUNK * BB * DD];   // 1 MB
__device__ __align__(16) float g_partT[NCHUNK * BB * DD];
__device__ __align__(16) float g_sumE[BB * DD];
__device__ __align__(16) float g_sumT[BB * DD];
__device__ __align__(16) unsigned char g_assign[PP * DD];   // part idx per (p,d)
__device__ float g_hsP[BB * NGRP];            // per (b,g): sum_d H_sd over 32 d's
__device__ float g_eP [BB * NGRP];            // per (b,g): sum_d SumE
__device__ float g_tP [BB * NGRP];            // per (b,g): sum_d SumT
__device__ float g_hpk[BB * PP];              // per (b,p): sum_k H_pk
__device__ int   g_cnt = 0;                   // k3 completion counter (self-resetting)

// ---------------------------------------------------------------------------
// k1: streaming pass over x (R8-proven shape) + hidden mask decode.
// grid = (NCHUNK, B) = 512 blocks, 512 threads, 16 LDG.128/thread.
// Blocks with b==0 first decode <=2 partitions' masks into g_assign
// (integer-only, 0.3 MB total — hidden in the 67 MB stream).
// Mask dtype detection per partition: u8 layout guarantees nonzero bytes at
// offset ≡1 (mod 4) in the partition's 3KB region (one true k per d); int32/
// float32 0/1 layout guarantees all-zero there; range in-bounds for both.
// ---------------------------------------------------------------------------
__global__ void __launch_bounds__(512) k1_stream(const float* __restrict__ x,
                                                 const void* __restrict__ masks_raw) {
    const int chunk = blockIdx.x;
    const int b     = blockIdx.y;
    const int t     = threadIdx.x;
    const int sub   = t >> 7;     // 0..3: row subset
    const int dt    = t & 127;    // float4 column

    // ---- hidden mask decode (blocks of batch 0 only; uniform per block) ----
    if (b == 0) {
        const unsigned int*  mw = (const unsigned int*)masks_raw;
        const unsigned char* m8 = (const unsigned char*)masks_raw;
        #pragma unroll
        for (int r = 0; r < 2; r++) {
            const int p = chunk + r * NCHUNK;      // covers 0..127 -> 98 used
            if (p < PP) {
                unsigned int v = 0;
                for (int j = t; j < MASK_WORDS_PER_P; j += 512)
                    v |= mw[p * MASK_WORDS_PER_P + j] & 0x0000FF00u;
                const bool isU8 = (__syncthreads_or(v != 0) != 0);
                int a = 0;
                #pragma unroll
                for (int k = KMAXP - 1; k >= 0; k--) {
                    const int idx = (p * KMAXP + k) * DD + t;
                    const bool mv = isU8 ? (m8[idx] != 0) : (mw[idx] != 0u);
                    if (mv) a = k;
                }
                g_assign[p * DD + t] = (unsigned char)a;
            }
        }
    }

    const float4* xp = reinterpret_cast<const float4*>(
        x + ((size_t)b * SS + (size_t)chunk * SROWS) * DD)
        + (size_t)sub * (DD / 4) + dt;

    float e0 = 0.f, e1 = 0.f, e2 = 0.f, e3 = 0.f;
    float t0 = 0.f, t1 = 0.f, t2 = 0.f, t3 = 0.f;
    #pragma unroll 4
    for (int i = 0; i < SROWS / 4; i++) {
        const float4 v = xp[(size_t)i * DD];   // advance 4 rows (= DD float4)
        const float p0 = __expf(v.x), p1 = __expf(v.y),
                    p2 = __expf(v.z), p3 = __expf(v.w);
        e0 += p0; e1 += p1; e2 += p2; e3 += p3;
        t0 = fmaf(p0, v.x, t0);
        t1 = fmaf(p1, v.y, t1);
        t2 = fmaf(p2, v.z, t2);
        t3 = fmaf(p3, v.w, t3);
    }

    __shared__ __align__(16) float4 sE[4][128], sT[4][128];
    sE[sub][dt] = make_float4(e0, e1, e2, e3);
    sT[sub][dt] = make_float4(t0, t1, t2, t3);
    __syncthreads();
    if (t < 128) {
        float4 ae = sE[0][t], at = sT[0][t];
        #pragma unroll
        for (int s = 1; s < 4; s++) {
            const float4 oe = sE[s][t], ot = sT[s][t];
            ae.x += oe.x; ae.y += oe.y; ae.z += oe.z; ae.w += oe.w;
            at.x += ot.x; at.y += ot.y; at.z += ot.z; at.w += ot.w;
        }
        const int base = (chunk * BB + b) * DD;   // chunk-major for k2 reads
        reinterpret_cast<float4*>(g_partE + base)[t] = ae;
        reinterpret_cast<float4*>(g_partT + base)[t] = at;
    }
}

// ---------------------------------------------------------------------------
// k2: chunk reduce + per-d singleton entropy + (b,g) partials.
// grid = (NGRP, B) = 128 blocks, 256 threads. (R8-proven.)
// ---------------------------------------------------------------------------
__global__ void __launch_bounds__(256) k2_reduce() {
    const int g    = blockIdx.x;
    const int b    = blockIdx.y;
    const int t    = threadIdx.x;
    const int seg  = t >> 5;      // 0..7
    const int lane = t & 31;
    const int d    = g * 32 + lane;

    float e = 0.f, tt = 0.f;
    #pragma unroll
    for (int i = 0; i < NCHUNK / 8; i++) {    // 8 chunks per segment
        const int c   = seg * (NCHUNK / 8) + i;
        const int idx = (c * BB + b) * DD + d;
        e  += g_partE[idx];
        tt += g_partT[idx];
    }

    __shared__ float sE[8][32], sT[8][32];
    sE[seg][lane] = e;
    sT[seg][lane] = tt;
    __syncthreads();

    if (seg == 0) {
        float E = 0.f, T = 0.f;
        #pragma unroll
        for (int s = 0; s < 8; s++) { E += sE[s][lane]; T += sT[s][lane]; }
        g_sumE[b * DD + d] = E;
        g_sumT[b * DD + d] = T;

        float h = logf(E) - T / E;            // singleton entropy for (b,d)

        float se = E, st = T, sh = h;
        #pragma unroll
        for (int o = 16; o > 0; o >>= 1) {
            se += __shfl_down_sync(0xffffffffu, se, o);
            st += __shfl_down_sync(0xffffffffu, st, o);
            sh += __shfl_down_sync(0xffffffffu, sh, o);
        }
        if (lane == 0) {
            g_hsP[b * NGRP + g] = sh;
            g_eP [b * NGRP + g] = se;
            g_tP [b * NGRP + g] = st;
        }
    }
}

// ---------------------------------------------------------------------------
// k3: sampled partitions (precomputed g_assign) + fused finalize.
// grid = (P, B) = 784 blocks, 128 threads x 4 d's. Last block (threadfence-
// reduction election) runs the k4 tail; counter self-resets for replays.
// ---------------------------------------------------------------------------
__global__ void __launch_bounds__(128) k3_parts(
    const float* __restrict__ es,  const float* __restrict__ iw,
    const float* __restrict__ W1,  const float* __restrict__ b1,
    const float* __restrict__ W2,  const float* __restrict__ b2,
    const float* __restrict__ W3,  const float* __restrict__ b3,
    float* __restrict__ out)
{
    const int p = blockIdx.x;
    const int b = blockIdx.y;
    const int t = threadIdx.x;

    const uchar4 a4 = reinterpret_cast<const uchar4*>(g_assign + p * DD)[t];
    const float4 e4 = reinterpret_cast<const float4*>(g_sumE + b * DD)[t];
    const float4 t4 = reinterpret_cast<const float4*>(g_sumT + b * DD)[t];

    float zk[KMAXP], tk[KMAXP];
    #pragma unroll
    for (int k = 0; k < KMAXP; k++) {
        zk[k] = (a4.x == k ? e4.x : 0.f) + (a4.y == k ? e4.y : 0.f)
              + (a4.z == k ? e4.z : 0.f) + (a4.w == k ? e4.w : 0.f);
        tk[k] = (a4.x == k ? t4.x : 0.f) + (a4.y == k ? t4.y : 0.f)
              + (a4.z == k ? t4.z : 0.f) + (a4.w == k ? t4.w : 0.f);
    }

    #pragma unroll
    for (int o = 16; o > 0; o >>= 1) {
        #pragma unroll
        for (int k = 0; k < KMAXP; k++) {
            zk[k] += __shfl_down_sync(0xffffffffu, zk[k], o);
            tk[k] += __shfl_down_sync(0xffffffffu, tk[k], o);
        }
    }
    __shared__ float sz[4][KMAXP], sst[4][KMAXP];
    const int w = t >> 5, l = t & 31;
    if (l == 0) {
        #pragma unroll
        for (int k = 0; k < KMAXP; k++) { sz[w][k] = zk[k]; sst[w][k] = tk[k]; }
    }
    __syncthreads();
    if (t == 0) {
        float hsum = 0.f;
        #pragma unroll
        for (int k = 0; k < KMAXP; k++) {
            float Z = sz[0][k] + sz[1][k] + sz[2][k] + sz[3][k];
            float T = sst[0][k] + sst[1][k] + sst[2][k] + sst[3][k];
            if (Z > 0.f) hsum += logf(Z) - T / Z;   // empty bin -> 0
        }
        g_hpk[b * PP + p] = hsum;
    }

    // ---- completion count: is this the last block? ----
    __shared__ int s_last;
    __threadfence();
    __syncthreads();
    if (t == 0) s_last = (atomicAdd(&g_cnt, 1) == PP * BB - 1);
    __syncthreads();
    if (!s_last) return;

    // ======================= k4 tail (one block) =======================
    __shared__ float sh_min[128];
    __shared__ float sh_es[128];
    __shared__ float shF[BB], shS[BB];
    __shared__ __align__(16) float sh_w2[16 * 32];
    __shared__ float sh_w1[32], sh_b1[32], sh_b2[16], sh_w3[16], sh_b3;
    __shared__ float sh_h1[32];

    // cooperative weight prefetch (issued first; overlaps partial loads)
    reinterpret_cast<float4*>(sh_w2)[t] = reinterpret_cast<const float4*>(W2)[t];
    if (t < 32) { sh_w1[t] = W1[t]; sh_b1[t] = b1[t]; }
    else if (t < 48) { sh_b2[t - 32] = b2[t - 32]; }
    else if (t < 64) { sh_w3[t - 48] = W3[t - 48]; }
    else if (t == 64) { sh_b3 = b3[0]; }

    if (t >= 96 && t < 96 + BB) {
        const int bb = t - 96;
        float hs = 0.f, E = 0.f, T = 0.f;
        #pragma unroll
        for (int g = 0; g < NGRP; g++) {
            hs += g_hsP[bb * NGRP + g];
            E  += g_eP [bb * NGRP + g];
            T  += g_tP [bb * NGRP + g];
        }
        shS[bb] = hs;
        shF[bb] = logf(E) - T / E;
    }

    float se = 0.f;
    #pragma unroll
    for (int i = 0; i < 4; i++) se += es[t + i * 128];
    sh_es[t] = se;
    __syncthreads();

    float wv = INFINITY;
    if (t < MAXPART) {
        float h;
        if (t == 0) {
            float s = 0.f;
            #pragma unroll
            for (int bb = 0; bb < BB; bb++) s += shF[bb];
            h = s / (float)BB;
        } else if (t == 1) {
            float s = 0.f;
            #pragma unroll
            for (int bb = 0; bb < BB; bb++) s += shS[bb];
            h = s / (float)BB;
        } else {
            float s = 0.f;
            #pragma unroll
            for (int bb = 0; bb < BB; bb++) s += g_hpk[bb * PP + (t - 2)];
            h = s / (float)BB;
        }
        const float sg = 1.f / (1.f + expf(-iw[t]));
        wv = h * sg;
    }
    sh_min[t] = wv;
    __syncthreads();

    #pragma unroll
    for (int o = 64; o > 0; o >>= 1) {
        if (t < o) {
            sh_min[t] = fminf(sh_min[t], sh_min[t + o]);
            sh_es[t] += sh_es[t + o];
        }
        __syncthreads();
    }

    if (t < 32) {
        float s = 0.f;
        #pragma unroll
        for (int bb = 0; bb < BB; bb++) s += shF[bb];
        const float h_whole = s / (float)BB;
        const float es_mean = sh_es[0] / (float)DD;

        const float raw_phi = es_mean * h_whole - sh_min[0];
        float z = fminf(fmaxf(raw_phi * 0.1f, 0.f), 1.f);

        sh_h1[t] = fmaxf(fmaf(z, sh_w1[t], sh_b1[t]), 0.f);   // h1, one per lane
        __syncwarp();

        float acc = 0.f;
        if (t < 16) {
            float a = sh_b2[t];
            #pragma unroll
            for (int j = 0; j < 32; j++) a = fmaf(sh_w2[t * 32 + j], sh_h1[j], a);
            acc = fmaxf(a, 0.f) * sh_w3[t];                    // h2[t] * W3[t]
        }
        #pragma unroll
        for (int o = 16; o > 0; o >>= 1) acc += __shfl_down_sync(0xffffffffu, acc, o);

        if (t == 0) {
            out[0] = 1.f / (1.f + expf(-(acc + sh_b3)));
            atomicExch(&g_cnt, 0);    // self-reset for the next graph replay
        }
    }
}

// ---------------------------------------------------------------------------
extern "C" void kernel_launch(void* const* d_in, const int* in_sizes, int n_in,
                              void* d_out, int out_size) {
    const float* x  = (const float*)d_in[0];
    const float* es = (const float*)d_in[1];
    const float* iw = (const float*)d_in[2];
    const float* W1 = (const float*)d_in[3];
    const float* b1 = (const float*)d_in[4];
    const float* W2 = (const float*)d_in[5];
    const float* b2 = (const float*)d_in[6];
    const float* W3 = (const float*)d_in[7];
    const float* b3 = (const float*)d_in[8];
    const void*  masks = (const void*)d_in[9];

    k1_stream<<<dim3(NCHUNK, BB), 512>>>(x, masks);
    k2_reduce<<<dim3(NGRP, BB), 256>>>();
    k3_parts<<<dim3(PP, BB), 128>>>(es, iw, W1, b1, W2, b2, W3, b3,
                                    (float*)d_out);
}